// round 1
// baseline (speedup 1.0000x reference)
#include <cuda_runtime.h>
#include <cstdint>

// VectorQuantizer: z_e (64,64,64,64) f32, emb (512,64) f32.
// M = 262144 points, D = 64, K = 512.
// Output (f32): [ z_q (N,D,H,W) : 16777216 ][ vq_loss : 1 ][ indices (N,H,W) : 262144 ]

#define KCODES   512
#define DDIM     64
#define HW       4096            // H*W
#define DHW      262144          // D*H*W
#define NPTS     262144          // N*H*W
#define EROW     68              // padded smem row stride (floats), 272B = 16B aligned
#define ZQ_OFF   0
#define LOSS_OFF 16777216
#define IDX_OFF  16777217

#define NBLOCKS  1024
#define NTHREADS 256

__device__ float g_partials[NBLOCKS];

__device__ __forceinline__ uint64_t pk2(float lo, float hi) {
    uint64_t r;
    asm("mov.b64 %0, {%1, %2};" : "=l"(r) : "f"(lo), "f"(hi));
    return r;
}
__device__ __forceinline__ float2 upk2(uint64_t v) {
    float2 r;
    asm("mov.b64 {%0, %1}, %2;" : "=f"(r.x), "=f"(r.y) : "l"(v));
    return r;
}
__device__ __forceinline__ void ffma2(uint64_t& d, uint64_t a, uint64_t b) {
    asm("fma.rn.f32x2 %0, %1, %2, %0;" : "+l"(d) : "l"(a), "l"(b));
}
__device__ __forceinline__ uint64_t fadd2(uint64_t a, uint64_t b) {
    uint64_t r;
    asm("add.rn.f32x2 %0, %1, %2;" : "=l"(r) : "l"(a), "l"(b));
    return r;
}

extern "C" __global__ void __launch_bounds__(NTHREADS, 1)
vq_kernel(const float* __restrict__ z, const float* __restrict__ emb,
          float* __restrict__ out)
{
    extern __shared__ float smem[];
    float* se   = smem;                    // KCODES * EROW floats
    float* sesq = smem + KCODES * EROW;    // KCODES floats
    float* sred = sesq + KCODES;           // 8 floats (warp partials)

    const int tid = threadIdx.x;

    // ---- load codebook into smem (padded rows), coalesced float4 ----
    {
        const float4* e4 = (const float4*)emb;           // 8192 float4
        for (int i = tid; i < KCODES * (DDIM / 4); i += NTHREADS) {
            int k = i >> 4;          // 16 float4 per row
            int j = i & 15;
            float4 v = e4[i];
            *(float4*)(se + k * EROW + 4 * j) = v;
        }
    }
    __syncthreads();

    // ---- e_sq per code ----
    for (int k = tid; k < KCODES; k += NTHREADS) {
        const float* r = se + k * EROW;
        float s = 0.f;
        #pragma unroll
        for (int d = 0; d < DDIM; d++) s = fmaf(r[d], r[d], s);
        sesq[k] = s;
    }
    __syncthreads();

    // ---- this thread's point ----
    const int p  = blockIdx.x * NTHREADS + tid;
    const int n  = p >> 12;
    const int hw = p & (HW - 1);
    const float* zbase = z + (size_t)n * DHW + hw;

    uint64_t zp[DDIM / 2];
    float zsq = 0.f;
    #pragma unroll
    for (int d = 0; d < DDIM; d += 2) {
        float a = zbase[(size_t)d * HW];
        float b = zbase[(size_t)(d + 1) * HW];
        zsq = fmaf(a, a, zsq);
        zsq = fmaf(b, b, zsq);
        zp[d >> 1] = pk2(a, b);
    }

    // ---- argmin over K: dist = (z_sq + e_sq[k]) - 2*dot ----
    float best = 3.4e38f;
    int   bidx = 0;
    #pragma unroll 2
    for (int k = 0; k < KCODES; k++) {
        const ulonglong2* e2 = (const ulonglong2*)(se + k * EROW);
        uint64_t a0 = 0ull, a1 = 0ull;   // packed (0.0f, 0.0f)
        #pragma unroll
        for (int j = 0; j < 16; j++) {
            ulonglong2 ee = e2[j];
            ffma2(a0, zp[2 * j],     ee.x);
            ffma2(a1, zp[2 * j + 1], ee.y);
        }
        float2 s = upk2(fadd2(a0, a1));
        float dot = s.x + s.y;
        float dist = fmaf(-2.0f, dot, zsq + sesq[k]);
        if (dist < best) { best = dist; bidx = k; }
    }

    // ---- epilogue: gather z_q, write, accumulate loss ----
    const float* eb = se + bidx * EROW;
    float* op = out + ZQ_OFF + (size_t)n * DHW + hw;
    float ls = 0.f;
    #pragma unroll
    for (int d = 0; d < DDIM; d += 2) {
        float2 zz = upk2(zp[d >> 1]);
        float v0 = eb[d];
        float v1 = eb[d + 1];
        op[(size_t)d * HW]       = v0;
        op[(size_t)(d + 1) * HW] = v1;
        float d0 = zz.x - v0;
        float d1 = zz.y - v1;
        ls = fmaf(d0, d0, ls);
        ls = fmaf(d1, d1, ls);
    }
    out[IDX_OFF + p] = (float)bidx;

    // ---- block-reduce loss (deterministic) ----
    #pragma unroll
    for (int off = 16; off > 0; off >>= 1)
        ls += __shfl_down_sync(0xFFFFFFFFu, ls, off);
    const int wid  = tid >> 5;
    const int lane = tid & 31;
    if (lane == 0) sred[wid] = ls;
    __syncthreads();
    if (tid == 0) {
        float s = 0.f;
        #pragma unroll
        for (int w = 0; w < NTHREADS / 32; w++) s += sred[w];
        g_partials[blockIdx.x] = s;
    }
}

extern "C" __global__ void vq_finalize(float* __restrict__ out)
{
    if (threadIdx.x == 0) {
        double s = 0.0;
        for (int i = 0; i < NBLOCKS; i++) s += (double)g_partials[i];
        out[LOSS_OFF] = (float)(s / 16777216.0);   // mean over M*D
    }
}

extern "C" void kernel_launch(void* const* d_in, const int* in_sizes, int n_in,
                              void* d_out, int out_size)
{
    const float* z   = (const float*)d_in[0];
    const float* emb = (const float*)d_in[1];
    if (n_in >= 2 && in_sizes[0] < in_sizes[1]) {   // safety: ensure z is the big one
        const float* t = z; z = emb; emb = t;
    }
    float* out = (float*)d_out;

    const int smem_bytes = (KCODES * EROW + KCODES + 8) * (int)sizeof(float); // 141,344
    static bool attr_set = false;
    if (!attr_set) {
        cudaFuncSetAttribute(vq_kernel, cudaFuncAttributeMaxDynamicSharedMemorySize,
                             smem_bytes);
        attr_set = true;
    }

    vq_kernel<<<NBLOCKS, NTHREADS, smem_bytes>>>(z, emb, out);
    vq_finalize<<<1, 32>>>(out);
}

// round 2
// speedup vs baseline: 1.2964x; 1.2964x over previous
#include <cuda_runtime.h>
#include <cstdint>

// VectorQuantizer: z_e (64,64,64,64) f32, emb (512,64) f32.
// M = 262144 points, D = 64, K = 512.
// Output (f32): [ z_q (N,D,H,W) : 16777216 ][ vq_loss : 1 ][ indices (N,H,W) : 262144 ]

#define KCODES   512
#define DDIM     64
#define HW       4096
#define DHW      262144
#define EROW     68              // padded smem row stride (floats), 272B, 16B aligned
#define ZQ_OFF   0
#define LOSS_OFF 16777216
#define IDX_OFF  16777217

#define NTHREADS 256
#define PTS_PER_THREAD 2
#define PTS_PER_BLOCK  (NTHREADS * PTS_PER_THREAD)   // 512
#define NBLOCKS  (262144 / PTS_PER_BLOCK)            // 512

__device__ float g_partials[NBLOCKS];

__device__ __forceinline__ uint64_t pk2(float lo, float hi) {
    uint64_t r;
    asm("mov.b64 %0, {%1, %2};" : "=l"(r) : "f"(lo), "f"(hi));
    return r;
}
__device__ __forceinline__ float2 upk2(uint64_t v) {
    float2 r;
    asm("mov.b64 {%0, %1}, %2;" : "=f"(r.x), "=f"(r.y) : "l"(v));
    return r;
}
__device__ __forceinline__ void ffma2(uint64_t& d, uint64_t a, uint64_t b) {
    asm("fma.rn.f32x2 %0, %1, %2, %0;" : "+l"(d) : "l"(a), "l"(b));
}
__device__ __forceinline__ uint64_t fadd2(uint64_t a, uint64_t b) {
    uint64_t r;
    asm("add.rn.f32x2 %0, %1, %2;" : "=l"(r) : "l"(a), "l"(b));
    return r;
}

extern "C" __global__ void __launch_bounds__(NTHREADS, 1)
vq_kernel(const float* __restrict__ z, const float* __restrict__ emb,
          float* __restrict__ out)
{
    extern __shared__ float smem[];
    float* se   = smem;                    // KCODES * EROW
    float* sesq = smem + KCODES * EROW;    // KCODES
    float* sred = sesq + KCODES;           // 8

    const int tid = threadIdx.x;

    // ---- codebook -> smem (padded rows), coalesced float4 ----
    {
        const float4* e4 = (const float4*)emb;           // 8192 float4
        for (int i = tid; i < KCODES * (DDIM / 4); i += NTHREADS) {
            int k = i >> 4;
            int j = i & 15;
            float4 v = e4[i];
            *(float4*)(se + k * EROW + 4 * j) = v;
        }
    }
    __syncthreads();

    // ---- e_sq per code ----
    for (int k = tid; k < KCODES; k += NTHREADS) {
        const float* r = se + k * EROW;
        float s = 0.f;
        #pragma unroll
        for (int d = 0; d < DDIM; d++) s = fmaf(r[d], r[d], s);
        sesq[k] = s;
    }
    __syncthreads();

    // ---- two points per thread (p1 = p0 + 256, same n) ----
    const int p0 = blockIdx.x * PTS_PER_BLOCK + tid;
    const int p1 = p0 + NTHREADS;
    const int n  = p0 >> 12;
    const int hw = p0 & (HW - 1);
    const float* zb0 = z + (size_t)n * DHW + hw;

    uint64_t zp0[DDIM / 2], zp1[DDIM / 2];
    float zsq0 = 0.f, zsq1 = 0.f;
    #pragma unroll
    for (int d = 0; d < DDIM; d += 2) {
        float a0 = zb0[(size_t)d * HW];
        float b0 = zb0[(size_t)(d + 1) * HW];
        float a1 = zb0[(size_t)d * HW + NTHREADS];
        float b1 = zb0[(size_t)(d + 1) * HW + NTHREADS];
        zsq0 = fmaf(a0, a0, zsq0); zsq0 = fmaf(b0, b0, zsq0);
        zsq1 = fmaf(a1, a1, zsq1); zsq1 = fmaf(b1, b1, zsq1);
        zp0[d >> 1] = pk2(a0, b0);
        zp1[d >> 1] = pk2(a1, b1);
    }

    // ---- argmin over K for both points ----
    float best0 = 3.4e38f, best1 = 3.4e38f;
    int   bidx0 = 0,       bidx1 = 0;
    for (int k = 0; k < KCODES; k++) {
        const ulonglong2* e2 = (const ulonglong2*)(se + k * EROW);
        uint64_t a00 = 0ull, a01 = 0ull, a10 = 0ull, a11 = 0ull;
        #pragma unroll
        for (int j = 0; j < 16; j++) {
            ulonglong2 ee = e2[j];
            ffma2(a00, zp0[2 * j],     ee.x);
            ffma2(a01, zp0[2 * j + 1], ee.y);
            ffma2(a10, zp1[2 * j],     ee.x);
            ffma2(a11, zp1[2 * j + 1], ee.y);
        }
        float esq = sesq[k];
        float2 s0 = upk2(fadd2(a00, a01));
        float2 s1 = upk2(fadd2(a10, a11));
        float dist0 = fmaf(-2.0f, s0.x + s0.y, zsq0 + esq);
        float dist1 = fmaf(-2.0f, s1.x + s1.y, zsq1 + esq);
        bool m0 = dist0 < best0;
        bool m1 = dist1 < best1;
        best0 = m0 ? dist0 : best0;  bidx0 = m0 ? k : bidx0;
        best1 = m1 ? dist1 : best1;  bidx1 = m1 ? k : bidx1;
    }

    // ---- epilogue: gather z_q, write, accumulate loss ----
    const float* eb0 = se + bidx0 * EROW;
    const float* eb1 = se + bidx1 * EROW;
    float* op = out + ZQ_OFF + (size_t)n * DHW + hw;
    float ls = 0.f;
    #pragma unroll
    for (int d = 0; d < DDIM; d += 2) {
        float2 z0 = upk2(zp0[d >> 1]);
        float2 z1 = upk2(zp1[d >> 1]);
        float v00 = eb0[d], v01 = eb0[d + 1];
        float v10 = eb1[d], v11 = eb1[d + 1];
        op[(size_t)d * HW]                  = v00;
        op[(size_t)(d + 1) * HW]            = v01;
        op[(size_t)d * HW + NTHREADS]       = v10;
        op[(size_t)(d + 1) * HW + NTHREADS] = v11;
        float d00 = z0.x - v00, d01 = z0.y - v01;
        float d10 = z1.x - v10, d11 = z1.y - v11;
        ls = fmaf(d00, d00, ls); ls = fmaf(d01, d01, ls);
        ls = fmaf(d10, d10, ls); ls = fmaf(d11, d11, ls);
    }
    out[IDX_OFF + p0] = (float)bidx0;
    out[IDX_OFF + p1] = (float)bidx1;

    // ---- block-reduce loss (deterministic fixed-order) ----
    #pragma unroll
    for (int off = 16; off > 0; off >>= 1)
        ls += __shfl_down_sync(0xFFFFFFFFu, ls, off);
    const int wid  = tid >> 5;
    const int lane = tid & 31;
    if (lane == 0) sred[wid] = ls;
    __syncthreads();
    if (tid == 0) {
        float s = 0.f;
        #pragma unroll
        for (int w = 0; w < NTHREADS / 32; w++) s += sred[w];
        g_partials[blockIdx.x] = s;
    }
}

extern "C" __global__ void __launch_bounds__(256, 1)
vq_finalize(float* __restrict__ out)
{
    __shared__ double sh[256];
    const int tid = threadIdx.x;
    // NBLOCKS = 512 partials, 2 per thread, fixed order -> deterministic
    double s = (double)g_partials[tid] + (double)g_partials[tid + 256];
    sh[tid] = s;
    __syncthreads();
    #pragma unroll
    for (int off = 128; off > 0; off >>= 1) {
        if (tid < off) sh[tid] += sh[tid + off];
        __syncthreads();
    }
    if (tid == 0) out[LOSS_OFF] = (float)(sh[0] / 16777216.0);  // mean over M*D
}

extern "C" void kernel_launch(void* const* d_in, const int* in_sizes, int n_in,
                              void* d_out, int out_size)
{
    const float* z   = (const float*)d_in[0];
    const float* emb = (const float*)d_in[1];
    if (n_in >= 2 && in_sizes[0] < in_sizes[1]) {
        const float* t = z; z = emb; emb = t;
    }
    float* out = (float*)d_out;

    const int smem_bytes = (KCODES * EROW + KCODES + 8) * (int)sizeof(float);
    static bool attr_set = false;
    if (!attr_set) {
        cudaFuncSetAttribute(vq_kernel, cudaFuncAttributeMaxDynamicSharedMemorySize,
                             smem_bytes);
        attr_set = true;
    }

    vq_kernel<<<NBLOCKS, NTHREADS, smem_bytes>>>(z, emb, out);
    vq_finalize<<<1, 256>>>(out);
}